// round 1
// baseline (speedup 1.0000x reference)
#include <cuda_runtime.h>
#include <math.h>
#include <stddef.h>

// Problem constants
namespace {
constexpr int B_ = 4, T_ = 2048, C_ = 1024, H_ = 4, D_ = 256;
constexpr int M_ = B_ * T_;   // 8192 rows (b*T + t)
constexpr int NG = 4 * C_;    // 4096 gate columns
}

// Scratch (static device globals; no allocation allowed)
__device__ float g_xc[(size_t)M_ * C_];        //  32 MB conv+silu output
__device__ float g_gates[(size_t)M_ * NG];     // 128 MB gate pre/post-activations
__device__ float g_h[(size_t)M_ * C_];         //  32 MB scan output
__device__ float g_hn[(size_t)M_ * C_];        //  32 MB group-normed
__device__ float g_sum[B_ * H_];
__device__ float g_sqs[B_ * H_];

// ---------------------------------------------------------------------------
// Stats zeroing (must run each launch; graph-replayed)
// ---------------------------------------------------------------------------
__global__ void zero_stats_kernel() {
    int i = threadIdx.x;
    if (i < B_ * H_) { g_sum[i] = 0.f; g_sqs[i] = 0.f; }
}

// ---------------------------------------------------------------------------
// Causal depthwise conv (k=4, left pad 3) + bias + SiLU
// xc[b,t,c] = silu( sum_k w[c,0,k] * x[b, t-3+k, c] + cb[c] )
// ---------------------------------------------------------------------------
__global__ void conv_silu_kernel(const float* __restrict__ x,
                                 const float* __restrict__ cw,
                                 const float* __restrict__ cb) {
    int idx = blockIdx.x * blockDim.x + threadIdx.x;   // over M_*C_
    int c = idx & (C_ - 1);
    int m = idx >> 10;            // b*T + t
    int t = m & (T_ - 1);
    const float* xp = x + (size_t)m * C_ + c;
    float v = cw[c * 4 + 3] * xp[0];
    if (t >= 1) v += cw[c * 4 + 2] * xp[-C_];
    if (t >= 2) v += cw[c * 4 + 1] * xp[-2 * C_];
    if (t >= 3) v += cw[c * 4 + 0] * xp[-3 * C_];
    v += cb[c];
    g_xc[idx] = v / (1.f + __expf(-v));
}

// ---------------------------------------------------------------------------
// Tiled fp32 GEMM, C[m,n] = sum_k A[m,k]*W[n,k]  (both K-contiguous, "NT")
// BM=BN=128, BK=16, 256 threads, 8x8 per thread, register prefetch.
// EPI=0: gates GEMM  (A=g_xc,  C=g_gates, bias=wx_b, tanh on gate block 2)
// EPI=1: output GEMM (A=g_hn,  C=d_out,   bias=out_b, + residual x)
// M,N multiples of 128, K multiple of 16 -> no bounds checks.
// ---------------------------------------------------------------------------
template <int EPI>
__global__ void __launch_bounds__(256, 2)
gemm_nt_kernel(const float* __restrict__ W,
               const float* __restrict__ bias,
               const float* __restrict__ resid,
               float* __restrict__ CoParam,
               int M, int N, int K) {
    constexpr int BM = 128, BN = 128, BK = 16;
    __shared__ float As[BK][BM + 4];
    __shared__ float Bs[BK][BN + 4];

    const float* A = (EPI == 0) ? g_xc : g_hn;
    float* Co = (EPI == 0) ? g_gates : CoParam;

    const int tid = threadIdx.x;
    const int bm = blockIdx.y * BM;
    const int bn = blockIdx.x * BN;
    const int lrow = tid >> 2;          // 0..63
    const int lcol = (tid & 3) << 2;    // 0,4,8,12

    const float* Ag = A + (size_t)(bm + lrow) * K + lcol;
    const float* Bg = W + (size_t)(bn + lrow) * K + lcol;

    float4 pa0 = *(const float4*)(Ag);
    float4 pa1 = *(const float4*)(Ag + (size_t)64 * K);
    float4 pb0 = *(const float4*)(Bg);
    float4 pb1 = *(const float4*)(Bg + (size_t)64 * K);

    float acc[8][8];
#pragma unroll
    for (int i = 0; i < 8; i++)
#pragma unroll
        for (int j = 0; j < 8; j++) acc[i][j] = 0.f;

    const int tx = tid & 15, ty = tid >> 4;

    for (int kt = 0; kt < K; kt += BK) {
        // commit prefetched tile to smem (A transposed to [k][m])
        As[lcol + 0][lrow] = pa0.x; As[lcol + 1][lrow] = pa0.y;
        As[lcol + 2][lrow] = pa0.z; As[lcol + 3][lrow] = pa0.w;
        As[lcol + 0][lrow + 64] = pa1.x; As[lcol + 1][lrow + 64] = pa1.y;
        As[lcol + 2][lrow + 64] = pa1.z; As[lcol + 3][lrow + 64] = pa1.w;
        Bs[lcol + 0][lrow] = pb0.x; Bs[lcol + 1][lrow] = pb0.y;
        Bs[lcol + 2][lrow] = pb0.z; Bs[lcol + 3][lrow] = pb0.w;
        Bs[lcol + 0][lrow + 64] = pb1.x; Bs[lcol + 1][lrow + 64] = pb1.y;
        Bs[lcol + 2][lrow + 64] = pb1.z; Bs[lcol + 3][lrow + 64] = pb1.w;
        __syncthreads();

        if (kt + BK < K) {   // issue next tile's global loads (overlap compute)
            pa0 = *(const float4*)(Ag + kt + BK);
            pa1 = *(const float4*)(Ag + (size_t)64 * K + kt + BK);
            pb0 = *(const float4*)(Bg + kt + BK);
            pb1 = *(const float4*)(Bg + (size_t)64 * K + kt + BK);
        }

#pragma unroll
        for (int kk = 0; kk < BK; kk++) {
            float4 a0 = *(const float4*)(&As[kk][ty * 8]);
            float4 a1 = *(const float4*)(&As[kk][ty * 8 + 4]);
            float4 b0 = *(const float4*)(&Bs[kk][tx * 8]);
            float4 b1 = *(const float4*)(&Bs[kk][tx * 8 + 4]);
            float av[8] = {a0.x, a0.y, a0.z, a0.w, a1.x, a1.y, a1.z, a1.w};
            float bv[8] = {b0.x, b0.y, b0.z, b0.w, b1.x, b1.y, b1.z, b1.w};
#pragma unroll
            for (int i = 0; i < 8; i++)
#pragma unroll
                for (int j = 0; j < 8; j++)
                    acc[i][j] = fmaf(av[i], bv[j], acc[i][j]);
        }
        __syncthreads();
    }

    const int row0 = bm + ty * 8;
    const int col0 = bn + tx * 8;
    const int gate = col0 >> 10;   // uniform across this thread's 8 columns
#pragma unroll
    for (int i = 0; i < 8; i++) {
        size_t ro = (size_t)(row0 + i) * N + col0;
#pragma unroll
        for (int j4 = 0; j4 < 2; j4++) {
            float4 v;
            float* vp = &v.x;
#pragma unroll
            for (int j = 0; j < 4; j++) {
                float t = acc[i][j4 * 4 + j] + bias[col0 + j4 * 4 + j];
                if (EPI == 0) {
                    if (gate == 2) t = tanhf(t);
                } else {
                    t += resid[ro + j4 * 4 + j];
                }
                vp[j] = t;
            }
            *(float4*)(&Co[ro + j4 * 4]) = v;
        }
    }
}

// ---------------------------------------------------------------------------
// sLSTM scan: one thread per (b,h,d) channel, sequential over T.
// Also accumulates per-(b,h) GroupNorm sum/sumsq via atomics.
// ---------------------------------------------------------------------------
__global__ void scan_kernel() {
    int tid = blockIdx.x * blockDim.x + threadIdx.x;   // 0..4095
    int b = tid >> 10;
    int hd = tid & 1023;
    const float* Gp = g_gates + (size_t)b * T_ * NG + hd;
    float* hp = g_h + (size_t)b * T_ * C_ + hd;

    float c = 0.f, n = 1.f, m = 0.f;
    float s1 = 0.f, s2 = 0.f;

#pragma unroll 4
    for (int t = 0; t < T_; t++) {
        const float* p = Gp + (size_t)t * NG;
        float ig = p[0];
        float fg = p[C_];
        float zg = p[2 * C_];   // tanh already applied in GEMM1 epilogue
        float og = p[3 * C_];

        float mn = fmaxf(fg + m, ig);
        float ip = __expf(ig - mn);
        float fp = __expf(fg + m - mn);
        c = fp * c + ip * zg;
        n = fp * n + ip;
        float sg = 1.f / (1.f + __expf(-og));
        float h = sg * c / (n + 1e-6f);
        hp[(size_t)t * C_] = h;
        s1 += h;
        s2 += h * h;
        m = mn;
    }
    int grp = (b << 2) + (hd >> 8);
    atomicAdd(&g_sum[grp], s1);
    atomicAdd(&g_sqs[grp], s2);
}

// ---------------------------------------------------------------------------
// GroupNorm apply: hn = (h - mean) * rstd * gn_w + gn_b
// mean/var recomputed per element from the 16 group counters (cheap).
// ---------------------------------------------------------------------------
__global__ void normalize_kernel(const float* __restrict__ gn_w,
                                 const float* __restrict__ gn_b) {
    int idx = blockIdx.x * blockDim.x + threadIdx.x;   // over M_*C_
    int c = idx & (C_ - 1);
    int bb = idx >> 21;        // idx / (T_*C_) ; T_*C_ = 2^21
    int grp = (bb << 2) + (c >> 8);
    const float inv_cnt = 1.f / (float)(T_ * D_);
    float mean = g_sum[grp] * inv_cnt;
    float var = g_sqs[grp] * inv_cnt - mean * mean;
    float rstd = rsqrtf(var + 1e-5f);
    float h = g_h[idx];
    g_hn[idx] = (h - mean) * rstd * gn_w[c] + gn_b[c];
}

// ---------------------------------------------------------------------------
// Launch
// ---------------------------------------------------------------------------
extern "C" void kernel_launch(void* const* d_in, const int* in_sizes, int n_in,
                              void* d_out, int out_size) {
    const float* x      = (const float*)d_in[0];
    const float* conv_w = (const float*)d_in[1];
    const float* conv_b = (const float*)d_in[2];
    const float* wx_w   = (const float*)d_in[3];
    const float* wx_b   = (const float*)d_in[4];
    const float* gn_w   = (const float*)d_in[5];
    const float* gn_b   = (const float*)d_in[6];
    const float* out_w  = (const float*)d_in[7];
    const float* out_b  = (const float*)d_in[8];
    float* out = (float*)d_out;

    (void)in_sizes; (void)n_in; (void)out_size;

    // 1) conv + silu
    conv_silu_kernel<<<(M_ * C_) / 256, 256>>>(x, conv_w, conv_b);

    // 2) gates GEMM (+bias, tanh on z block)
    {
        dim3 g(NG / 128, M_ / 128);
        gemm_nt_kernel<0><<<g, 256>>>(wx_w, wx_b, nullptr, nullptr, M_, NG, C_);
    }

    // 3) zero stats, 4) scan (+GroupNorm stats)
    zero_stats_kernel<<<1, 32>>>();
    scan_kernel<<<32, 128>>>();

    // 5) GroupNorm apply
    normalize_kernel<<<(M_ * C_) / 256, 256>>>(gn_w, gn_b);

    // 6) output GEMM (+bias, +residual x) -> d_out
    {
        dim3 g(C_ / 128, M_ / 128);
        gemm_nt_kernel<1><<<g, 256>>>(out_w, out_b, x, out, M_, C_, C_);
    }
}

// round 2
// speedup vs baseline: 1.8325x; 1.8325x over previous
#include <cuda_runtime.h>
#include <math.h>
#include <stddef.h>
#include <stdint.h>

// Problem constants
namespace {
constexpr int B_ = 4, T_ = 2048, C_ = 1024, H_ = 4, D_ = 256;
constexpr int M_ = B_ * T_;   // 8192 rows (b*T + t)
constexpr int NG = 4 * C_;    // 4096 gate columns
}

// Scratch (static device globals; no allocation allowed)
__device__ float g_xc[(size_t)M_ * C_];        //  32 MB conv+silu output
__device__ float g_gates[(size_t)M_ * NG];     // 128 MB gate activations
__device__ float g_h[(size_t)M_ * C_];         //  32 MB scan output
__device__ float g_sum[B_ * H_];
__device__ float g_sqs[B_ * H_];
__device__ float g_ns[B_ * C_];                // per-(b,c) norm scale
__device__ float g_nt[B_ * C_];                // per-(b,c) norm shift

__device__ __forceinline__ float to_tf32(float x) {
    uint32_t u;
    asm("cvt.rna.tf32.f32 %0, %1;" : "=r"(u) : "f"(x));
    return __uint_as_float(u);
}

// ---------------------------------------------------------------------------
// Stats zeroing
// ---------------------------------------------------------------------------
__global__ void zero_stats_kernel() {
    int i = threadIdx.x;
    if (i < B_ * H_) { g_sum[i] = 0.f; g_sqs[i] = 0.f; }
}

// ---------------------------------------------------------------------------
// Causal depthwise conv (k=4, left pad 3) + bias + SiLU
// ---------------------------------------------------------------------------
__global__ void conv_silu_kernel(const float* __restrict__ x,
                                 const float* __restrict__ cw,
                                 const float* __restrict__ cb) {
    int idx = blockIdx.x * blockDim.x + threadIdx.x;   // over M_*C_
    int c = idx & (C_ - 1);
    int m = idx >> 10;            // b*T + t
    int t = m & (T_ - 1);
    const float* xp = x + (size_t)m * C_ + c;
    float v = cw[c * 4 + 3] * xp[0];
    if (t >= 1) v += cw[c * 4 + 2] * xp[-C_];
    if (t >= 2) v += cw[c * 4 + 1] * xp[-2 * C_];
    if (t >= 3) v += cw[c * 4 + 0] * xp[-3 * C_];
    v += cb[c];
    g_xc[idx] = v / (1.f + __expf(-v));
}

// ---------------------------------------------------------------------------
// TF32 tensor-core GEMM:  C[m,n] = sum_k A[m,k] * W[n,k]   ("NT", K-contig)
// BM=BN=128, BK=16, 256 threads (8 warps of 64x32), mma.sync.m16n8k8.
// EPI=0: gates GEMM  (A=g_xc, C=g_gates, bias=wx_b, tanh on gate block 2)
// EPI=1: out GEMM    (A=GroupNorm(g_h) fused at load, C=d_out, +out_b, +x)
// ---------------------------------------------------------------------------
template <int EPI>
__global__ void __launch_bounds__(256, 2)
gemm_tf32_kernel(const float* __restrict__ W,
                 const float* __restrict__ bias,
                 const float* __restrict__ resid,
                 float* __restrict__ CoParam,
                 int M, int N, int K) {
    constexpr int BK = 16;
    __shared__ float As[128][BK + 4];   // stride 20: conflict-free frags+stores
    __shared__ float Bs[128][BK + 4];

    const float* A = (EPI == 0) ? g_xc : g_h;
    float* Co = (EPI == 0) ? g_gates : CoParam;

    const int tid = threadIdx.x;
    const int bm = blockIdx.y * 128;
    const int bn = blockIdx.x * 128;
    const int lrow = tid >> 2;          // 0..63
    const int lcol = (tid & 3) << 2;    // 0,4,8,12

    const float* Ag = A + (size_t)(bm + lrow) * K + lcol;
    const float* Bg = W + (size_t)(bn + lrow) * K + lcol;
    const float* Sp = g_ns + (bm >> 11) * C_ + lcol;   // EPI==1 only
    const float* Tp = g_nt + (bm >> 11) * C_ + lcol;

    float4 pa0, pa1, pb0, pb1;
    {
        pa0 = *(const float4*)(Ag);
        pa1 = *(const float4*)(Ag + (size_t)64 * K);
        pb0 = *(const float4*)(Bg);
        pb1 = *(const float4*)(Bg + (size_t)64 * K);
        if (EPI == 1) {
            float4 s = *(const float4*)(Sp);
            float4 t = *(const float4*)(Tp);
            pa0.x = pa0.x * s.x + t.x; pa0.y = pa0.y * s.y + t.y;
            pa0.z = pa0.z * s.z + t.z; pa0.w = pa0.w * s.w + t.w;
            pa1.x = pa1.x * s.x + t.x; pa1.y = pa1.y * s.y + t.y;
            pa1.z = pa1.z * s.z + t.z; pa1.w = pa1.w * s.w + t.w;
        }
    }

    const int wid = tid >> 5;
    const int lane = tid & 31;
    const int wm = (wid & 1) * 64;      // warp row offset
    const int wn = (wid >> 1) * 32;     // warp col offset
    const int qr = lane >> 2;           // 0..7
    const int qc = lane & 3;            // 0..3

    float acc[4][4][4];
#pragma unroll
    for (int i = 0; i < 4; i++)
#pragma unroll
        for (int j = 0; j < 4; j++)
#pragma unroll
            for (int k = 0; k < 4; k++) acc[i][j][k] = 0.f;

    for (int kt = 0; kt < K; kt += BK) {
        // commit prefetched tile (convert to tf32)
        *(float4*)(&As[lrow][lcol]) =
            make_float4(to_tf32(pa0.x), to_tf32(pa0.y), to_tf32(pa0.z), to_tf32(pa0.w));
        *(float4*)(&As[lrow + 64][lcol]) =
            make_float4(to_tf32(pa1.x), to_tf32(pa1.y), to_tf32(pa1.z), to_tf32(pa1.w));
        *(float4*)(&Bs[lrow][lcol]) =
            make_float4(to_tf32(pb0.x), to_tf32(pb0.y), to_tf32(pb0.z), to_tf32(pb0.w));
        *(float4*)(&Bs[lrow + 64][lcol]) =
            make_float4(to_tf32(pb1.x), to_tf32(pb1.y), to_tf32(pb1.z), to_tf32(pb1.w));
        __syncthreads();

        if (kt + BK < K) {   // prefetch next tile
            int k2 = kt + BK;
            pa0 = *(const float4*)(Ag + k2);
            pa1 = *(const float4*)(Ag + (size_t)64 * K + k2);
            pb0 = *(const float4*)(Bg + k2);
            pb1 = *(const float4*)(Bg + (size_t)64 * K + k2);
            if (EPI == 1) {
                float4 s = *(const float4*)(Sp + k2);
                float4 t = *(const float4*)(Tp + k2);
                pa0.x = pa0.x * s.x + t.x; pa0.y = pa0.y * s.y + t.y;
                pa0.z = pa0.z * s.z + t.z; pa0.w = pa0.w * s.w + t.w;
                pa1.x = pa1.x * s.x + t.x; pa1.y = pa1.y * s.y + t.y;
                pa1.z = pa1.z * s.z + t.z; pa1.w = pa1.w * s.w + t.w;
            }
        }

#pragma unroll
        for (int kk0 = 0; kk0 < BK; kk0 += 8) {
            uint32_t af[4][4], bf[4][2];
#pragma unroll
            for (int mt = 0; mt < 4; mt++) {
                int r = wm + mt * 16 + qr;
                af[mt][0] = __float_as_uint(As[r][kk0 + qc]);
                af[mt][1] = __float_as_uint(As[r + 8][kk0 + qc]);
                af[mt][2] = __float_as_uint(As[r][kk0 + qc + 4]);
                af[mt][3] = __float_as_uint(As[r + 8][kk0 + qc + 4]);
            }
#pragma unroll
            for (int nt = 0; nt < 4; nt++) {
                int r = wn + nt * 8 + qr;
                bf[nt][0] = __float_as_uint(Bs[r][kk0 + qc]);
                bf[nt][1] = __float_as_uint(Bs[r][kk0 + qc + 4]);
            }
#pragma unroll
            for (int mt = 0; mt < 4; mt++)
#pragma unroll
                for (int nt = 0; nt < 4; nt++) {
                    float* c = acc[mt][nt];
                    asm volatile(
                        "mma.sync.aligned.m16n8k8.row.col.f32.tf32.tf32.f32 "
                        "{%0,%1,%2,%3}, {%4,%5,%6,%7}, {%8,%9}, {%0,%1,%2,%3};"
                        : "+f"(c[0]), "+f"(c[1]), "+f"(c[2]), "+f"(c[3])
                        : "r"(af[mt][0]), "r"(af[mt][1]), "r"(af[mt][2]), "r"(af[mt][3]),
                          "r"(bf[nt][0]), "r"(bf[nt][1]));
                }
        }
        __syncthreads();
    }

    // Epilogue. Within a block the gate index (col>>10) is uniform.
    const int gate = bn >> 10;
#pragma unroll
    for (int mt = 0; mt < 4; mt++) {
#pragma unroll
        for (int nt = 0; nt < 4; nt++) {
            int r0 = bm + wm + mt * 16 + qr;
            int cc = bn + wn + nt * 8 + 2 * qc;
            float2 bb = *(const float2*)(&bias[cc]);
            float v0 = acc[mt][nt][0] + bb.x;
            float v1 = acc[mt][nt][1] + bb.y;
            float v2 = acc[mt][nt][2] + bb.x;
            float v3 = acc[mt][nt][3] + bb.y;
            size_t o0 = (size_t)r0 * N + cc;
            size_t o1 = (size_t)(r0 + 8) * N + cc;
            if (EPI == 0) {
                if (gate == 2) {
                    v0 = tanhf(v0); v1 = tanhf(v1);
                    v2 = tanhf(v2); v3 = tanhf(v3);
                }
            } else {
                float2 r0v = *(const float2*)(&resid[o0]);
                float2 r1v = *(const float2*)(&resid[o1]);
                v0 += r0v.x; v1 += r0v.y;
                v2 += r1v.x; v3 += r1v.y;
            }
            *(float2*)(&Co[o0]) = make_float2(v0, v1);
            *(float2*)(&Co[o1]) = make_float2(v2, v3);
        }
    }
}

// ---------------------------------------------------------------------------
// sLSTM scan: one thread per (b,h,d) channel; next-t prefetch for MLP.
// Accumulates per-(b,h) GroupNorm sum/sumsq via atomics.
// ---------------------------------------------------------------------------
__global__ void scan_kernel() {
    int tid = blockIdx.x * blockDim.x + threadIdx.x;   // 0..4095
    int b = tid >> 10;
    int hd = tid & 1023;
    const float* Gp = g_gates + (size_t)b * T_ * NG + hd;
    float* hp = g_h + (size_t)b * T_ * C_ + hd;

    float c = 0.f, n = 1.f, m = 0.f;
    float s1 = 0.f, s2 = 0.f;

    float ig = Gp[0], fg = Gp[C_], zg = Gp[2 * C_], og = Gp[3 * C_];

    for (int t = 0; t < T_; t++) {
        float nig = 0.f, nfg = 0.f, nzg = 0.f, nog = 0.f;
        if (t + 1 < T_) {
            const float* p = Gp + (size_t)(t + 1) * NG;
            nig = p[0]; nfg = p[C_]; nzg = p[2 * C_]; nog = p[3 * C_];
        }
        float mn = fmaxf(fg + m, ig);
        float ip = __expf(ig - mn);
        float fp = __expf(fg + m - mn);
        c = fp * c + ip * zg;
        n = fp * n + ip;
        float sg = 1.f / (1.f + __expf(-og));
        float h = __fdividef(sg * c, n + 1e-6f);
        hp[(size_t)t * C_] = h;
        s1 += h;
        s2 += h * h;
        m = mn;
        ig = nig; fg = nfg; zg = nzg; og = nog;
    }
    int grp = (b << 2) + (hd >> 8);
    atomicAdd(&g_sum[grp], s1);
    atomicAdd(&g_sqs[grp], s2);
}

// ---------------------------------------------------------------------------
// Precompute per-(b,c) GroupNorm scale/shift:  hn = h*s + t
// ---------------------------------------------------------------------------
__global__ void prep_norm_kernel(const float* __restrict__ gn_w,
                                 const float* __restrict__ gn_b) {
    int idx = blockIdx.x * blockDim.x + threadIdx.x;   // over B_*C_
    int b = idx >> 10;
    int c = idx & (C_ - 1);
    int grp = (b << 2) + (c >> 8);
    const float inv_cnt = 1.f / (float)(T_ * D_);
    float mean = g_sum[grp] * inv_cnt;
    float var = g_sqs[grp] * inv_cnt - mean * mean;
    float rstd = rsqrtf(var + 1e-5f);
    float s = rstd * gn_w[c];
    g_ns[idx] = s;
    g_nt[idx] = gn_b[c] - mean * s;
}

// ---------------------------------------------------------------------------
// Launch
// ---------------------------------------------------------------------------
extern "C" void kernel_launch(void* const* d_in, const int* in_sizes, int n_in,
                              void* d_out, int out_size) {
    const float* x      = (const float*)d_in[0];
    const float* conv_w = (const float*)d_in[1];
    const float* conv_b = (const float*)d_in[2];
    const float* wx_w   = (const float*)d_in[3];
    const float* wx_b   = (const float*)d_in[4];
    const float* gn_w   = (const float*)d_in[5];
    const float* gn_b   = (const float*)d_in[6];
    const float* out_w  = (const float*)d_in[7];
    const float* out_b  = (const float*)d_in[8];
    float* out = (float*)d_out;

    (void)in_sizes; (void)n_in; (void)out_size;

    // 1) conv + silu
    conv_silu_kernel<<<(M_ * C_) / 256, 256>>>(x, conv_w, conv_b);

    // 2) gates GEMM (+bias, tanh on z block)
    {
        dim3 g(NG / 128, M_ / 128);
        gemm_tf32_kernel<0><<<g, 256>>>(wx_w, wx_b, nullptr, nullptr, M_, NG, C_);
    }

    // 3) zero stats, 4) scan (+GroupNorm stats), 5) norm coefficients
    zero_stats_kernel<<<1, 32>>>();
    scan_kernel<<<32, 128>>>();
    prep_norm_kernel<<<B_ * C_ / 256, 256>>>(gn_w, gn_b);

    // 6) output GEMM (GroupNorm fused at A-load, +bias, +residual) -> d_out
    {
        dim3 g(C_ / 128, M_ / 128);
        gemm_tf32_kernel<1><<<g, 256>>>(out_w, out_b, x, out, M_, C_, C_);
    }
}